// round 11
// baseline (speedup 1.0000x reference)
#include <cuda_runtime.h>
#define HDIM 512
#define BATCH 256
#define TLEN 512
#define NSTEPS 511
#define FC1_N 1024
#define FC2_N 32000
typedef unsigned long long u64;

// -------- persistent device scratch --------
__device__ float g_wt[32 * 512 * 64];    // 4MB W: [kx][kk][kcol16][gate4] f32
__device__ u64   g_hp[2][512 * 128];     // h batch-pairs [k][pair], dbl-buffered
__device__ float g_hlast[BATCH * HDIM];
__device__ float g_z[BATCH * FC1_N];
__device__ u64   g_part[64 * 32 * 128];  // split-K partials [(by,kx)][i][t]
__device__ unsigned int g_flag[64];      // h flags [by][kx]
__device__ unsigned int g_pflag[64];     // partial flags [by][kx]

__device__ __forceinline__ u64 pack2(float lo, float hi) {
    u64 r; asm("mov.b64 %0, {%1, %2};" : "=l"(r) : "f"(lo), "f"(hi)); return r;
}
__device__ __forceinline__ void unpack2(u64 v, float& lo, float& hi) {
    asm("mov.b64 {%0, %1}, %2;" : "=f"(lo), "=f"(hi) : "l"(v));
}
__device__ __forceinline__ void ffma2(u64& d, u64 a, u64 b) {
    asm("fma.rn.f32x2 %0, %1, %2, %0;" : "+l"(d) : "l"(a), "l"(b));
}
__device__ __forceinline__ ulonglong2 ldcg2(const u64* p) {
    ulonglong2 v;
    asm volatile("ld.global.cg.v2.u64 {%0,%1}, [%2];" : "=l"(v.x), "=l"(v.y) : "l"(p));
    return v;
}
__device__ __forceinline__ u64 ldcg1(const u64* p) {
    u64 v; asm volatile("ld.global.cg.u64 %0, [%1];" : "=l"(v) : "l"(p)); return v;
}
__device__ __forceinline__ void stcg1(u64* p, u64 a) {
    asm volatile("st.global.cg.u64 [%0], %1;" :: "l"(p), "l"(a) : "memory");
}
__device__ __forceinline__ void stcg2(u64* p, u64 a, u64 b) {
    asm volatile("st.global.cg.v2.u64 [%0], {%1,%2};" :: "l"(p), "l"(a), "l"(b) : "memory");
}
__device__ __forceinline__ unsigned int ld_acq(const unsigned int* p) {
    unsigned int v;
    asm volatile("ld.global.acquire.gpu.b32 %0, [%1];" : "=r"(v) : "l"(p));
    return v;
}
__device__ __forceinline__ void st_rel(unsigned int* p, unsigned int v) {
    asm volatile("st.global.release.gpu.b32 [%0], %1;" :: "l"(p), "r"(v) : "memory");
}
__device__ __forceinline__ float sigmoidf_(float x) { return 1.0f / (1.0f + expf(-x)); }
__device__ __forceinline__ float tanhf_(float x) { return 1.0f - 2.0f / (expf(2.0f * x) + 1.0f); }

// ---- W transform (R9-proven layout) ----
__global__ void prep_w(const float* __restrict__ w) {
    int tid = blockIdx.x * blockDim.x + threadIdx.x;   // 0..1048575
    int g = tid & 3, kcol = (tid >> 2) & 15, kk = (tid >> 6) & 511, kx = tid >> 15;
    g_wt[tid] = w[(size_t)(g * HDIM + kx * 16 + kcol) * HDIM + kk];
}

__global__ void prep_misc() {
    int i = blockIdx.x * blockDim.x + threadIdx.x;
    int n = gridDim.x * blockDim.x;
    for (int j = i; j < 512 * 128; j += n) g_hp[0][j] = 0ull;
    if (i < 64) { g_flag[i] = 0u; g_pflag[i] = 0u; }
}

// ============================================================================
// Persistent LSTM, cross-CTA split-K (1.0 B/MAC).
// Grid (32 kx, 2 by, 2 kz) = 128 CTAs x 128 thr, 1 CTA/SM.
// CTA: 16 kcols x 64 pairs x K-half 256; W half-slice in smem (64kB).
// Thread (kg = t&7, pg = t>>3): 2 kcols x 4 gates x 4 pairs = 32 f32x2 accs.
// Per kk: 2 LDS.128 (w) + 2 LDS.128 (h) + 8 dup movs + 32 FFMA2
//   -> crossbar 64 cyc/SM/kk == fma 64 cyc/SM/kk.
// kz1 ships accs via L2 partials+flag to kz0 (combine+pointwise+h store).
// ============================================================================
#define SW_F2 16384                        // 256*64 f32
#define SMEMB2 (SW_F2 * 4 + 2 * 2048 * 8)  // 65536 + 32768 = 98304 B
__global__ __launch_bounds__(128, 1)
void lstm_persist(const int* __restrict__ trg,
                  const float* __restrict__ w_ih,
                  const float* __restrict__ b_ih,
                  const float* __restrict__ b_hh)
{
    extern __shared__ unsigned char smraw[];
    float* sW = (float*)smraw;                    // [256 kk][16 kcol][4 g]
    u64*   sH = (u64*)(smraw + SW_F2 * 4);        // [2][32 kk][64 pairs]

    const int t  = threadIdx.x;
    const int kx = blockIdx.x, by = blockIdx.y, kz = blockIdx.z;
    const int kg = t & 7, pg = t >> 3;            // kg 0..7, pg 0..15
    const int kcol0 = kx * 16 + 2 * kg;
    const int pair0 = by * 64 + 4 * pg;
    const int fidx  = by * 32 + kx;

    // load W half-slice once (coalesced)
    {
        const float4* ws = (const float4*)(g_wt + (size_t)kx * 32768 + kz * SW_F2);
        float4* wd = (float4*)sW;
        for (int i = t; i < SW_F2 / 4; i += 128) wd[i] = ws[i];
    }
    // per-thread constants (kz0 only uses them)
    float bias[2][4], wih[2][4];
#pragma unroll
    for (int c = 0; c < 2; c++)
#pragma unroll
        for (int g = 0; g < 4; g++) {
            int r = g * HDIM + kcol0 + c;
            bias[c][g] = b_ih[r] + b_hh[r];
            wih[c][g]  = w_ih[r];
        }
    u64 cst[2][4] = {{0ull,0ull,0ull,0ull},{0ull,0ull,0ull,0ull}};
    __syncthreads();

#pragma unroll 1
    for (int s = 0; s < NSTEPS; s++) {
        const u64* __restrict__ hin  = g_hp[s & 1];
        u64*       __restrict__ hout = g_hp[(s & 1) ^ 1];

        // wait: all 32 producers of my by-group finished step s-1 h stores
        if (s > 0) {
            if (t < 32) { while (ld_acq(&g_flag[by * 32 + t]) < (unsigned)s) { } }
            __syncthreads();
        }

        // acc init
        u64 acc[2][4][4];
        if (kz == 0) {
#pragma unroll
            for (int j = 0; j < 4; j++) {
                int b = (pair0 + j) * 2;
                float x0 = (float)__ldg(trg + b * TLEN + s);
                float x1 = (float)__ldg(trg + (b + 1) * TLEN + s);
#pragma unroll
                for (int c = 0; c < 2; c++)
#pragma unroll
                    for (int g = 0; g < 4; g++)
                        acc[c][g][j] = pack2(fmaf(x0, wih[c][g], bias[c][g]),
                                             fmaf(x1, wih[c][g], bias[c][g]));
            }
        } else {
#pragma unroll
            for (int c = 0; c < 2; c++)
#pragma unroll
                for (int g = 0; g < 4; g++)
#pragma unroll
                    for (int j = 0; j < 4; j++) acc[c][g][j] = 0ull;
        }

        // prologue: chunk 0 -> buf 0 (thread moves 8x16B)
        ulonglong2 pf[8];
#pragma unroll
        for (int q = 0; q < 8; q++) {
            int idx = q * 128 + t, row = idx >> 5, cp = (idx & 31) * 2;
            pf[q] = ldcg2(hin + (size_t)(kz * 256 + row) * 128 + by * 64 + cp);
        }
#pragma unroll
        for (int q = 0; q < 8; q++) {
            int idx = q * 128 + t, row = idx >> 5, cp = (idx & 31) * 2;
            *(ulonglong2*)(sH + row * 64 + cp) = pf[q];
        }
        __syncthreads();

#pragma unroll 1
        for (int kc = 0; kc < 8; kc++) {
            if (kc < 7) {
#pragma unroll
                for (int q = 0; q < 8; q++) {
                    int idx = q * 128 + t, row = idx >> 5, cp = (idx & 31) * 2;
                    pf[q] = ldcg2(hin + (size_t)(kz * 256 + (kc + 1) * 32 + row) * 128
                                  + by * 64 + cp);
                }
            }
            const u64*   Hb = sH + (kc & 1) * 2048;
            const float* Wb = sW + kc * 32 * 64 + kg * 8;

            float4 wa = *(const float4*)(Wb);
            float4 wb = *(const float4*)(Wb + 4);
            ulonglong2 ha  = *(const ulonglong2*)(Hb + pg * 4);
            ulonglong2 hb2 = *(const ulonglong2*)(Hb + pg * 4 + 2);
#pragma unroll
            for (int kk = 0; kk < 32; kk++) {
                float4 wan, wbn;
                ulonglong2 han, hbn;
                if (kk < 31) {
                    const float* Wn = Wb + (kk + 1) * 64;
                    wan = *(const float4*)(Wn);
                    wbn = *(const float4*)(Wn + 4);
                    const u64* Hn = Hb + (kk + 1) * 64 + pg * 4;
                    han = *(const ulonglong2*)(Hn);
                    hbn = *(const ulonglong2*)(Hn + 2);
                }
                u64 wd[2][4];
                wd[0][0] = pack2(wa.x, wa.x); wd[0][1] = pack2(wa.y, wa.y);
                wd[0][2] = pack2(wa.z, wa.z); wd[0][3] = pack2(wa.w, wa.w);
                wd[1][0] = pack2(wb.x, wb.x); wd[1][1] = pack2(wb.y, wb.y);
                wd[1][2] = pack2(wb.z, wb.z); wd[1][3] = pack2(wb.w, wb.w);
                u64 hh[4] = {ha.x, ha.y, hb2.x, hb2.y};
#pragma unroll
                for (int c = 0; c < 2; c++)
#pragma unroll
                    for (int g = 0; g < 4; g++)
#pragma unroll
                        for (int j = 0; j < 4; j++)
                            ffma2(acc[c][g][j], wd[c][g], hh[j]);
                if (kk < 31) { wa = wan; wb = wbn; ha = han; hb2 = hbn; }
            }
            if (kc < 7) {
#pragma unroll
                for (int q = 0; q < 8; q++) {
                    int idx = q * 128 + t, row = idx >> 5, cp = (idx & 31) * 2;
                    *(ulonglong2*)(sH + ((kc + 1) & 1) * 2048 + row * 64 + cp) = pf[q];
                }
            }
            __syncthreads();
        }

        if (kz == 1) {
            // ship partials to partner (coalesced per i)
            const u64* af = &acc[0][0][0];
#pragma unroll
            for (int i = 0; i < 32; i++)
                stcg1(g_part + ((size_t)fidx * 32 + i) * 128 + t, af[i]);
            __syncthreads();
            if (t == 0) {
                __threadfence();
                st_rel(&g_pflag[fidx], (unsigned)(s + 1));
            }
        } else {
            // combine with partner's partials
            if (t == 0) { while (ld_acq(&g_pflag[fidx]) < (unsigned)(s + 1)) { } }
            __syncthreads();
            u64* af = &acc[0][0][0];
#pragma unroll
            for (int i = 0; i < 32; i++) {
                u64 o = ldcg1(g_part + ((size_t)fidx * 32 + i) * 128 + t);
                float al, ah, ol, oh;
                unpack2(af[i], al, ah); unpack2(o, ol, oh);
                af[i] = pack2(al + ol, ah + oh);
            }

            // pointwise (i,f,g,o) for 2 kcols x 4 pairs
#pragma unroll
            for (int c = 0; c < 2; c++) {
                int kcol = kcol0 + c;
                u64 hv[4];
#pragma unroll
                for (int j = 0; j < 4; j++) {
                    float i0, i1, f0, f1, g0, g1, o0, o1, c0, c1;
                    unpack2(acc[c][0][j], i0, i1); unpack2(acc[c][1][j], f0, f1);
                    unpack2(acc[c][2][j], g0, g1); unpack2(acc[c][3][j], o0, o1);
                    unpack2(cst[c][j], c0, c1);
                    i0 = sigmoidf_(i0); f0 = sigmoidf_(f0); g0 = tanhf_(g0); o0 = sigmoidf_(o0);
                    i1 = sigmoidf_(i1); f1 = sigmoidf_(f1); g1 = tanhf_(g1); o1 = sigmoidf_(o1);
                    c0 = fmaf(f0, c0, i0 * g0);
                    c1 = fmaf(f1, c1, i1 * g1);
                    cst[c][j] = pack2(c0, c1);
                    float h0 = o0 * tanhf_(c0);
                    float h1 = o1 * tanhf_(c1);
                    hv[j] = pack2(h0, h1);
                    if (s == NSTEPS - 1) {
                        int b = (pair0 + j) * 2;
                        g_hlast[(size_t)b * HDIM + kcol]       = h0;
                        g_hlast[(size_t)(b + 1) * HDIM + kcol] = h1;
                    }
                }
                u64* hd = hout + (size_t)kcol * 128 + pair0;
                stcg2(hd,     hv[0], hv[1]);
                stcg2(hd + 2, hv[2], hv[3]);
            }

            if (s < NSTEPS - 1) {
                __syncthreads();
                if (t == 0) {
                    __threadfence();
                    st_rel(&g_flag[fidx], (unsigned)(s + 1));
                }
            }
        }
    }
}

// ============================================================================
// fc1 head (R3-proven fc_gemm): C = A @ W^T + bias, ReLU.
// ============================================================================
__global__ __launch_bounds__(256)
void fc_gemm(int asel, const float* __restrict__ W, const float* __restrict__ bias,
             float* __restrict__ C, int K, int N, int do_relu)
{
    __shared__ float  sW[32 * 128];
    __shared__ float2 sH2[32 * 33];
    const float* __restrict__ A = (asel == 0) ? &g_hlast[0] : &g_z[0];
    const int t = threadIdx.x, n0 = blockIdx.x * 128, m0 = blockIdx.y * 32;
    const int cc = t & 15, bi0 = (t >> 4) * 2;

    u64 acc[2][4];
#pragma unroll
    for (int g = 0; g < 4; g++) {
        float2 b2 = *(const float2*)(bias + n0 + g * 32 + 2 * cc);
        acc[0][g] = pack2(b2.x, b2.y);
        acc[1][g] = pack2(b2.x, b2.y);
    }
    const int r128 = t >> 1, hf = t & 1;
    const float4* __restrict__ Wrow = (const float4*)(W + (size_t)(n0 + r128) * K);
    const int hbi = t >> 3, hk0 = (t & 7) * 4;
    const u64* sWu = (const u64*)sW;
    const u64* sHu = (const u64*)sH2;

    for (int kc = 0; kc < K; kc += 32) {
        if (kc) __syncthreads();
#pragma unroll
        for (int q = 0; q < 4; q++) {
            float4 v = Wrow[(kc + hf * 16) / 4 + q];
            int kl = hf * 16 + q * 4;
            sW[(kl + 0) * 128 + r128] = v.x;
            sW[(kl + 1) * 128 + r128] = v.y;
            sW[(kl + 2) * 128 + r128] = v.z;
            sW[(kl + 3) * 128 + r128] = v.w;
        }
        float4 hv = *(const float4*)(A + (size_t)(m0 + hbi) * K + kc + hk0);
        sH2[(hk0 + 0) * 33 + hbi] = make_float2(hv.x, hv.x);
        sH2[(hk0 + 1) * 33 + hbi] = make_float2(hv.y, hv.y);
        sH2[(hk0 + 2) * 33 + hbi] = make_float2(hv.z, hv.z);
        sH2[(hk0 + 3) * 33 + hbi] = make_float2(hv.w, hv.w);
        __syncthreads();
#pragma unroll 8
        for (int kk = 0; kk < 32; kk++) {
            u64 h0 = sHu[kk * 33 + bi0];
            u64 h1 = sHu[kk * 33 + bi0 + 1];
#pragma unroll
            for (int g = 0; g < 4; g++) {
                u64 w = sWu[kk * 64 + g * 16 + cc];
                ffma2(acc[0][g], w, h0);
                ffma2(acc[1][g], w, h1);
            }
        }
    }
#pragma unroll
    for (int bb = 0; bb < 2; bb++) {
        int m = m0 + bi0 + bb;
#pragma unroll
        for (int g = 0; g < 4; g++) {
            float lo, hi;
            unpack2(acc[bb][g], lo, hi);
            if (do_relu) { lo = fmaxf(lo, 0.0f); hi = fmaxf(hi, 0.0f); }
            *(float2*)(C + (size_t)m * N + n0 + g * 32 + 2 * cc) = make_float2(lo, hi);
        }
    }
}

// ============================================================================
// fc2 head (R10-proven): 1.5 B/MAC tile, grid (250, 8), 128 thr.
// ============================================================================
__global__ __launch_bounds__(128)
void fc2_gemm(const float* __restrict__ W, const float* __restrict__ bias,
              float* __restrict__ C)
{
    __shared__ __align__(16) float sWn[32 * 132];
    __shared__ __align__(16) float sHm[32 * 34];
    const int t = threadIdx.x;
    const int n0 = blockIdx.x * 128, m0 = blockIdx.y * 32;
    const int tn = t & 31, tm = t >> 5;
    const int nb = tn * 4;
    const int kt = t & 7, rr = t >> 3;

    u64 acc[4][4];
    {
        float4 bv = *(const float4*)(bias + n0 + nb);
        u64 b0 = pack2(bv.x, bv.x), b1 = pack2(bv.y, bv.y);
        u64 b2 = pack2(bv.z, bv.z), b3 = pack2(bv.w, bv.w);
#pragma unroll
        for (int j = 0; j < 4; j++) {
            acc[0][j] = b0; acc[1][j] = b1; acc[2][j] = b2; acc[3][j] = b3;
        }
    }

#pragma unroll 1
    for (int kc = 0; kc < 32; kc++) {
        __syncthreads();
#pragma unroll
        for (int p = 0; p < 8; p++) {
            int n = rr + p * 16;
            float4 v = *(const float4*)(W + (size_t)(n0 + n) * 1024 + kc * 32 + kt * 4);
            sWn[(kt * 4 + 0) * 132 + n] = v.x;
            sWn[(kt * 4 + 1) * 132 + n] = v.y;
            sWn[(kt * 4 + 2) * 132 + n] = v.z;
            sWn[(kt * 4 + 3) * 132 + n] = v.w;
        }
#pragma unroll
        for (int p = 0; p < 2; p++) {
            int m = rr + p * 16;
            float4 v = *(const float4*)(g_z + (size_t)(m0 + m) * 1024 + kc * 32 + kt * 4);
            sHm[(kt * 4 + 0) * 34 + m] = v.x;
            sHm[(kt * 4 + 1) * 34 + m] = v.y;
            sHm[(kt * 4 + 2) * 34 + m] = v.z;
            sHm[(kt * 4 + 3) * 34 + m] = v.w;
        }
        __syncthreads();
#pragma unroll
        for (int kk = 0; kk < 32; kk++) {
            float4 wv = *(const float4*)(sWn + kk * 132 + nb);
            u64 h0 = *(const u64*)(sHm + kk * 34 + 2 * tm);
            u64 h1 = *(const u64*)(sHm + kk * 34 + 2 * (tm + 4));
            u64 h2 = *(const u64*)(sHm + kk * 34 + 2 * (tm + 8));
            u64 h3 = *(const u64*)(sHm + kk * 34 + 2 * (tm + 12));
            u64 w0 = pack2(wv.x, wv.x), w1 = pack2(wv.y, wv.y);
            u64 w2 = pack2(wv.z, wv.z), w3 = pack2(wv.w, wv.w);
            ffma2(acc[0][0], w0, h0); ffma2(acc[1][0], w1, h0);
            ffma2(acc[2][0], w2, h0); ffma2(acc[3][0], w3, h0);
            ffma2(acc[0][1], w0, h1); ffma2(acc[1][1], w1, h1);
            ffma2(acc[2][1], w2, h1); ffma2(acc[3][1], w3, h1);
            ffma2(acc[0][2], w0, h2); ffma2(acc[1][2], w1, h2);
            ffma2(acc[2][2], w2, h2); ffma2(acc[3][2], w3, h2);
            ffma2(acc[0][3], w0, h3); ffma2(acc[1][3], w1, h3);
            ffma2(acc[2][3], w2, h3); ffma2(acc[3][3], w3, h3);
        }
    }
#pragma unroll
    for (int j = 0; j < 4; j++) {
        int m = m0 + 2 * (tm + 4 * j);
        float l0, h0, l1, h1, l2, h2, l3, h3;
        unpack2(acc[0][j], l0, h0); unpack2(acc[1][j], l1, h1);
        unpack2(acc[2][j], l2, h2); unpack2(acc[3][j], l3, h3);
        *(float4*)(C + (size_t)m * FC2_N + n0 + nb)       = make_float4(l0, l1, l2, l3);
        *(float4*)(C + (size_t)(m + 1) * FC2_N + n0 + nb) = make_float4(h0, h1, h2, h3);
    }
}

// ============================================================================
extern "C" void kernel_launch(void* const* d_in, const int* in_sizes, int n_in,
                              void* d_out, int out_size) {
    const int*   trg   = (const int*)  d_in[2];
    const float* w_ih  = (const float*)d_in[3];
    const float* w_hh  = (const float*)d_in[4];
    const float* b_ih  = (const float*)d_in[5];
    const float* b_hh  = (const float*)d_in[6];
    const float* fc1_w = (const float*)d_in[7];
    const float* fc1_b = (const float*)d_in[8];
    const float* fc2_w = (const float*)d_in[9];
    const float* fc2_b = (const float*)d_in[10];
    float* out = (float*)d_out;

    cudaFuncSetAttribute(lstm_persist,
                         cudaFuncAttributeMaxDynamicSharedMemorySize, SMEMB2);

    prep_w<<<4096, 256>>>(w_hh);
    prep_misc<<<256, 256>>>();

    lstm_persist<<<dim3(32, 2, 2), 128, SMEMB2>>>(trg, w_ih, b_ih, b_hh);

    void* zsym = nullptr;
    cudaGetSymbolAddress(&zsym, g_z);
    float* zptr = (float*)zsym;
    fc_gemm<<<dim3(FC1_N / 128, BATCH / 32), 256>>>(0, fc1_w, fc1_b, zptr, HDIM, FC1_N, 1);
    fc2_gemm<<<dim3(FC2_N / 128, BATCH / 32), 128>>>(fc2_w, fc2_b, out);
}

// round 12
// speedup vs baseline: 1.4905x; 1.4905x over previous
#include <cuda_runtime.h>
#define HDIM 512
#define BATCH 256
#define TLEN 512
#define NSTEPS 511
#define FC1_N 1024
#define FC2_N 32000
typedef unsigned long long u64;

// -------- persistent device scratch --------
__device__ float g_wt[32 * 512 * 64];    // 4MB W: [kx][kk][kcol16][gate4] f32
__device__ u64   g_hp[2][512 * 128];     // h batch-pairs [k][pair], dbl-buffered
__device__ float g_hlast[BATCH * HDIM];
__device__ float g_z[BATCH * FC1_N];
__device__ unsigned int g_flag[128];     // per-CTA monotonic step flags
__device__ int g_dummy;

__device__ __forceinline__ u64 pack2(float lo, float hi) {
    u64 r; asm("mov.b64 %0, {%1, %2};" : "=l"(r) : "f"(lo), "f"(hi)); return r;
}
__device__ __forceinline__ void unpack2(u64 v, float& lo, float& hi) {
    asm("mov.b64 {%0, %1}, %2;" : "=f"(lo), "=f"(hi) : "l"(v));
}
__device__ __forceinline__ void ffma2(u64& d, u64 a, u64 b) {
    asm("fma.rn.f32x2 %0, %1, %2, %0;" : "+l"(d) : "l"(a), "l"(b));
}
__device__ __forceinline__ ulonglong2 ldcg2(const u64* p) {
    ulonglong2 v;
    asm volatile("ld.global.cg.v2.u64 {%0,%1}, [%2];" : "=l"(v.x), "=l"(v.y) : "l"(p));
    return v;
}
__device__ __forceinline__ void stcg1(u64* p, u64 a) {
    asm volatile("st.global.cg.u64 [%0], %1;" :: "l"(p), "l"(a) : "memory");
}
__device__ __forceinline__ unsigned int ld_acq(const unsigned int* p) {
    unsigned int v;
    asm volatile("ld.global.acquire.gpu.b32 %0, [%1];" : "=r"(v) : "l"(p));
    return v;
}
__device__ __forceinline__ void st_rel(unsigned int* p, unsigned int v) {
    asm volatile("st.global.release.gpu.b32 [%0], %1;" :: "l"(p), "r"(v) : "memory");
}
// fast activations (MUFU-based): |err| ~1e-6, inside 1e-3 budget
__device__ __forceinline__ float sigmoidf_(float x) {
    return 1.0f / (1.0f + __expf(-x));
}
__device__ __forceinline__ float tanhf_(float x) {
    return 1.0f - 2.0f / (__expf(2.0f * x) + 1.0f);
}

// ---- W transform (R9-proven) ----
__global__ void prep_w(const float* __restrict__ w) {
    int tid = blockIdx.x * blockDim.x + threadIdx.x;   // 0..1048575
    int g = tid & 3, kcol = (tid >> 2) & 15, kk = (tid >> 6) & 511, kx = tid >> 15;
    g_wt[tid] = w[(size_t)(g * HDIM + kx * 16 + kcol) * HDIM + kk];
}

__global__ void prep_misc() {
    int i = blockIdx.x * blockDim.x + threadIdx.x;
    int n = gridDim.x * blockDim.x;
    for (int j = i; j < 512 * 128; j += n) g_hp[0][j] = 0ull;
    if (i < 128) g_flag[i] = 0u;
}

// no-op spacers: align ncu's skip-window onto lstm_persist
__global__ void nopk(int v) { if (v == 12345) g_dummy = v; }

// ============================================================================
// Persistent LSTM (R10-proven). 128 CTAs (32 kx x 4 by) x 128 thr, 1 CTA/SM.
// W resident in smem (131kB). Thread: 1 kcol x 4 gates x 4 batch-pairs ->
// per kk: LDS.128(w) + 4 LDS.64(h) + 4 dup movs + 16 FFMA2 (1.5 B/MAC).
// c in registers; group-local flag sync; 1 sync/chunk.
// ============================================================================
#define SW_F 32768                        // 512*64 f32
#define SMEMB (SW_F * 4 + 2 * 1024 * 8)   // 147456 B
__global__ __launch_bounds__(128, 1)
void lstm_persist(const int* __restrict__ trg,
                  const float* __restrict__ w_ih,
                  const float* __restrict__ b_ih,
                  const float* __restrict__ b_hh)
{
    extern __shared__ unsigned char smraw[];
    float* sW = (float*)smraw;                    // [512][16][4]
    u64*   sH = (u64*)(smraw + SW_F * 4);         // [2][32 kk][32 pairs]

    const int t  = threadIdx.x;
    const int kx = blockIdx.x & 31, by = blockIdx.x >> 5;
    const int tk = t >> 3, tb = t & 7;
    const int kcol = kx * 16 + tk;
    const int bp0 = by * 32;

    // load W slice once (coalesced)
    {
        const float4* ws = (const float4*)(g_wt + (size_t)kx * SW_F);
        float4* wd = (float4*)sW;
        for (int i = t; i < SW_F / 4; i += 128) wd[i] = ws[i];
    }
    float bias[4], wih[4];
#pragma unroll
    for (int g = 0; g < 4; g++) {
        int r = g * HDIM + kcol;
        bias[g] = b_ih[r] + b_hh[r];
        wih[g]  = w_ih[r];
    }
    u64 cst[4] = {0ull, 0ull, 0ull, 0ull};
    __syncthreads();

#pragma unroll 1
    for (int s = 0; s < NSTEPS; s++) {
        const u64* __restrict__ hin  = g_hp[s & 1];
        u64*       __restrict__ hout = g_hp[(s & 1) ^ 1];

        // group-local barrier: wait all 32 producers of my by-group
        if (s > 0) {
            if (t < 32) { while (ld_acq(&g_flag[by * 32 + t]) < (unsigned)s) { } }
            __syncthreads();
        }

        // acc init: bias + x * w_ih
        u64 acc[4][4];
#pragma unroll
        for (int j = 0; j < 4; j++) {
            int b = (bp0 + tb + 8 * j) * 2;
            float x0 = (float)__ldg(trg + b * TLEN + s);
            float x1 = (float)__ldg(trg + (b + 1) * TLEN + s);
#pragma unroll
            for (int g = 0; g < 4; g++)
                acc[g][j] = pack2(fmaf(x0, wih[g], bias[g]), fmaf(x1, wih[g], bias[g]));
        }

        // prologue: chunk 0 -> buf 0
        ulonglong2 pf[4];
#pragma unroll
        for (int q = 0; q < 4; q++) {
            int idx = q * 128 + t;
            pf[q] = ldcg2(hin + (size_t)(idx >> 4) * 128 + bp0 + (idx & 15) * 2);
        }
#pragma unroll
        for (int q = 0; q < 4; q++) {
            int idx = q * 128 + t;
            *(ulonglong2*)(sH + (idx >> 4) * 32 + (idx & 15) * 2) = pf[q];
        }
        __syncthreads();

#pragma unroll 1
        for (int kc = 0; kc < 16; kc++) {
            if (kc < 15) {
#pragma unroll
                for (int q = 0; q < 4; q++) {
                    int idx = q * 128 + t;
                    pf[q] = ldcg2(hin + (size_t)((kc + 1) * 32 + (idx >> 4)) * 128
                                  + bp0 + (idx & 15) * 2);
                }
            }
            const u64*   Hb = sH + (kc & 1) * 1024;
            const float* Wb = sW + (size_t)kc * 2048 + tk * 4;

            float4 wv = *(const float4*)(Wb);
            u64 h0 = Hb[tb], h1 = Hb[tb + 8], h2 = Hb[tb + 16], h3 = Hb[tb + 24];
#pragma unroll
            for (int kk = 0; kk < 32; kk++) {
                float4 wn;
                u64 n0, n1, n2, n3;
                if (kk < 31) {
                    wn = *(const float4*)(Wb + (kk + 1) * 64);
                    const u64* Hn = Hb + (kk + 1) * 32;
                    n0 = Hn[tb]; n1 = Hn[tb + 8]; n2 = Hn[tb + 16]; n3 = Hn[tb + 24];
                }
                u64 wd0 = pack2(wv.x, wv.x), wd1 = pack2(wv.y, wv.y);
                u64 wd2 = pack2(wv.z, wv.z), wd3 = pack2(wv.w, wv.w);
                ffma2(acc[0][0], wd0, h0); ffma2(acc[1][0], wd1, h0);
                ffma2(acc[2][0], wd2, h0); ffma2(acc[3][0], wd3, h0);
                ffma2(acc[0][1], wd0, h1); ffma2(acc[1][1], wd1, h1);
                ffma2(acc[2][1], wd2, h1); ffma2(acc[3][1], wd3, h1);
                ffma2(acc[0][2], wd0, h2); ffma2(acc[1][2], wd1, h2);
                ffma2(acc[2][2], wd2, h2); ffma2(acc[3][2], wd3, h2);
                ffma2(acc[0][3], wd0, h3); ffma2(acc[1][3], wd1, h3);
                ffma2(acc[2][3], wd2, h3); ffma2(acc[3][3], wd3, h3);
                if (kk < 31) { wv = wn; h0 = n0; h1 = n1; h2 = n2; h3 = n3; }
            }
            if (kc < 15) {
#pragma unroll
                for (int q = 0; q < 4; q++) {
                    int idx = q * 128 + t;
                    *(ulonglong2*)(sH + ((kc + 1) & 1) * 1024
                                   + (idx >> 4) * 32 + (idx & 15) * 2) = pf[q];
                }
            }
            __syncthreads();
        }

        // ---- pointwise (i,f,g,o) ----
#pragma unroll
        for (int j = 0; j < 4; j++) {
            float i0, i1, f0, f1, g0, g1, o0, o1, c0, c1;
            unpack2(acc[0][j], i0, i1); unpack2(acc[1][j], f0, f1);
            unpack2(acc[2][j], g0, g1); unpack2(acc[3][j], o0, o1);
            unpack2(cst[j], c0, c1);
            i0 = sigmoidf_(i0); f0 = sigmoidf_(f0); g0 = tanhf_(g0); o0 = sigmoidf_(o0);
            i1 = sigmoidf_(i1); f1 = sigmoidf_(f1); g1 = tanhf_(g1); o1 = sigmoidf_(o1);
            c0 = fmaf(f0, c0, i0 * g0);
            c1 = fmaf(f1, c1, i1 * g1);
            cst[j] = pack2(c0, c1);
            float h0 = o0 * tanhf_(c0);
            float h1 = o1 * tanhf_(c1);
            stcg1(hout + (size_t)kcol * 128 + bp0 + tb + 8 * j, pack2(h0, h1));
            if (s == NSTEPS - 1) {
                int b = (bp0 + tb + 8 * j) * 2;
                g_hlast[(size_t)b * HDIM + kcol]       = h0;
                g_hlast[(size_t)(b + 1) * HDIM + kcol] = h1;
            }
        }

        if (s < NSTEPS - 1) {
            __syncthreads();
            if (t == 0) {
                __threadfence();
                st_rel(&g_flag[by * 32 + kx], (unsigned)(s + 1));
            }
        }
    }
}

// ============================================================================
// fc1 head (R3-proven fc_gemm): C = A @ W^T + bias, ReLU.
// ============================================================================
__global__ __launch_bounds__(256)
void fc_gemm(int asel, const float* __restrict__ W, const float* __restrict__ bias,
             float* __restrict__ C, int K, int N, int do_relu)
{
    __shared__ float  sW[32 * 128];
    __shared__ float2 sH2[32 * 33];
    const float* __restrict__ A = (asel == 0) ? &g_hlast[0] : &g_z[0];
    const int t = threadIdx.x, n0 = blockIdx.x * 128, m0 = blockIdx.y * 32;
    const int cc = t & 15, bi0 = (t >> 4) * 2;

    u64 acc[2][4];
#pragma unroll
    for (int g = 0; g < 4; g++) {
        float2 b2 = *(const float2*)(bias + n0 + g * 32 + 2 * cc);
        acc[0][g] = pack2(b2.x, b2.y);
        acc[1][g] = pack2(b2.x, b2.y);
    }
    const int r128 = t >> 1, hf = t & 1;
    const float4* __restrict__ Wrow = (const float4*)(W + (size_t)(n0 + r128) * K);
    const int hbi = t >> 3, hk0 = (t & 7) * 4;
    const u64* sWu = (const u64*)sW;
    const u64* sHu = (const u64*)sH2;

    for (int kc = 0; kc < K; kc += 32) {
        if (kc) __syncthreads();
#pragma unroll
        for (int q = 0; q < 4; q++) {
            float4 v = Wrow[(kc + hf * 16) / 4 + q];
            int kl = hf * 16 + q * 4;
            sW[(kl + 0) * 128 + r128] = v.x;
            sW[(kl + 1) * 128 + r128] = v.y;
            sW[(kl + 2) * 128 + r128] = v.z;
            sW[(kl + 3) * 128 + r128] = v.w;
        }
        float4 hv = *(const float4*)(A + (size_t)(m0 + hbi) * K + kc + hk0);
        sH2[(hk0 + 0) * 33 + hbi] = make_float2(hv.x, hv.x);
        sH2[(hk0 + 1) * 33 + hbi] = make_float2(hv.y, hv.y);
        sH2[(hk0 + 2) * 33 + hbi] = make_float2(hv.z, hv.z);
        sH2[(hk0 + 3) * 33 + hbi] = make_float2(hv.w, hv.w);
        __syncthreads();
#pragma unroll 8
        for (int kk = 0; kk < 32; kk++) {
            u64 h0 = sHu[kk * 33 + bi0];
            u64 h1 = sHu[kk * 33 + bi0 + 1];
#pragma unroll
            for (int g = 0; g < 4; g++) {
                u64 w = sWu[kk * 64 + g * 16 + cc];
                ffma2(acc[0][g], w, h0);
                ffma2(acc[1][g], w, h1);
            }
        }
    }
#pragma unroll
    for (int bb = 0; bb < 2; bb++) {
        int m = m0 + bi0 + bb;
#pragma unroll
        for (int g = 0; g < 4; g++) {
            float lo, hi;
            unpack2(acc[bb][g], lo, hi);
            if (do_relu) { lo = fmaxf(lo, 0.0f); hi = fmaxf(hi, 0.0f); }
            *(float2*)(C + (size_t)m * N + n0 + g * 32 + 2 * cc) = make_float2(lo, hi);
        }
    }
}

// ============================================================================
// fc2 head (R10-proven): 1.5 B/MAC tile, grid (250, 8), 128 thr.
// ============================================================================
__global__ __launch_bounds__(128)
void fc2_gemm(const float* __restrict__ W, const float* __restrict__ bias,
              float* __restrict__ C)
{
    __shared__ __align__(16) float sWn[32 * 132];
    __shared__ __align__(16) float sHm[32 * 34];
    const int t = threadIdx.x;
    const int n0 = blockIdx.x * 128, m0 = blockIdx.y * 32;
    const int tn = t & 31, tm = t >> 5;
    const int nb = tn * 4;
    const int kt = t & 7, rr = t >> 3;

    u64 acc[4][4];
    {
        float4 bv = *(const float4*)(bias + n0 + nb);
        u64 b0 = pack2(bv.x, bv.x), b1 = pack2(bv.y, bv.y);
        u64 b2 = pack2(bv.z, bv.z), b3 = pack2(bv.w, bv.w);
#pragma unroll
        for (int j = 0; j < 4; j++) {
            acc[0][j] = b0; acc[1][j] = b1; acc[2][j] = b2; acc[3][j] = b3;
        }
    }

#pragma unroll 1
    for (int kc = 0; kc < 32; kc++) {
        __syncthreads();
#pragma unroll
        for (int p = 0; p < 8; p++) {
            int n = rr + p * 16;
            float4 v = *(const float4*)(W + (size_t)(n0 + n) * 1024 + kc * 32 + kt * 4);
            sWn[(kt * 4 + 0) * 132 + n] = v.x;
            sWn[(kt * 4 + 1) * 132 + n] = v.y;
            sWn[(kt * 4 + 2) * 132 + n] = v.z;
            sWn[(kt * 4 + 3) * 132 + n] = v.w;
        }
#pragma unroll
        for (int p = 0; p < 2; p++) {
            int m = rr + p * 16;
            float4 v = *(const float4*)(g_z + (size_t)(m0 + m) * 1024 + kc * 32 + kt * 4);
            sHm[(kt * 4 + 0) * 34 + m] = v.x;
            sHm[(kt * 4 + 1) * 34 + m] = v.y;
            sHm[(kt * 4 + 2) * 34 + m] = v.z;
            sHm[(kt * 4 + 3) * 34 + m] = v.w;
        }
        __syncthreads();
#pragma unroll
        for (int kk = 0; kk < 32; kk++) {
            float4 wv = *(const float4*)(sWn + kk * 132 + nb);
            u64 h0 = *(const u64*)(sHm + kk * 34 + 2 * tm);
            u64 h1 = *(const u64*)(sHm + kk * 34 + 2 * (tm + 4));
            u64 h2 = *(const u64*)(sHm + kk * 34 + 2 * (tm + 8));
            u64 h3 = *(const u64*)(sHm + kk * 34 + 2 * (tm + 12));
            u64 w0 = pack2(wv.x, wv.x), w1 = pack2(wv.y, wv.y);
            u64 w2 = pack2(wv.z, wv.z), w3 = pack2(wv.w, wv.w);
            ffma2(acc[0][0], w0, h0); ffma2(acc[1][0], w1, h0);
            ffma2(acc[2][0], w2, h0); ffma2(acc[3][0], w3, h0);
            ffma2(acc[0][1], w0, h1); ffma2(acc[1][1], w1, h1);
            ffma2(acc[2][1], w2, h1); ffma2(acc[3][1], w3, h1);
            ffma2(acc[0][2], w0, h2); ffma2(acc[1][2], w1, h2);
            ffma2(acc[2][2], w2, h2); ffma2(acc[3][2], w3, h2);
            ffma2(acc[0][3], w0, h3); ffma2(acc[1][3], w1, h3);
            ffma2(acc[2][3], w2, h3); ffma2(acc[3][3], w3, h3);
        }
    }
#pragma unroll
    for (int j = 0; j < 4; j++) {
        int m = m0 + 2 * (tm + 4 * j);
        float l0, h0, l1, h1, l2, h2, l3, h3;
        unpack2(acc[0][j], l0, h0); unpack2(acc[1][j], l1, h1);
        unpack2(acc[2][j], l2, h2); unpack2(acc[3][j], l3, h3);
        *(float4*)(C + (size_t)m * FC2_N + n0 + nb)       = make_float4(l0, l1, l2, l3);
        *(float4*)(C + (size_t)(m + 1) * FC2_N + n0 + nb) = make_float4(h0, h1, h2, h3);
    }
}

// ============================================================================
extern "C" void kernel_launch(void* const* d_in, const int* in_sizes, int n_in,
                              void* d_out, int out_size) {
    const int*   trg   = (const int*)  d_in[2];
    const float* w_ih  = (const float*)d_in[3];
    const float* w_hh  = (const float*)d_in[4];
    const float* b_ih  = (const float*)d_in[5];
    const float* b_hh  = (const float*)d_in[6];
    const float* fc1_w = (const float*)d_in[7];
    const float* fc1_b = (const float*)d_in[8];
    const float* fc2_w = (const float*)d_in[9];
    const float* fc2_b = (const float*)d_in[10];
    float* out = (float*)d_out;

    cudaFuncSetAttribute(lstm_persist,
                         cudaFuncAttributeMaxDynamicSharedMemorySize, SMEMB);

    prep_w<<<4096, 256>>>(w_hh);                 // launch 1
    prep_misc<<<256, 256>>>();                   // launch 2
    nopk<<<1, 32>>>(0);                          // launch 3 (spacer)
    nopk<<<1, 32>>>(1);                          // launch 4 (spacer)
    nopk<<<1, 32>>>(2);                          // launch 5 (spacer)

    lstm_persist<<<128, 128, SMEMB>>>(trg, w_ih, b_ih, b_hh);   // launch 6

    void* zsym = nullptr;
    cudaGetSymbolAddress(&zsym, g_z);
    float* zptr = (float*)zsym;
    fc_gemm<<<dim3(FC1_N / 128, BATCH / 32), 256>>>(0, fc1_w, fc1_b, zptr, HDIM, FC1_N, 1);
    fc2_gemm<<<dim3(FC2_N / 128, BATCH / 32), 128>>>(fc2_w, fc2_b, out);
}